// round 6
// baseline (speedup 1.0000x reference)
#include <cuda_runtime.h>

#define KK    64
#define S1C   5
#define CC    128
#define MM    320         // KK*S1C
#define PP    1936        // 44*44
#define NN    8
#define PT    64          // pixels per tile
#define TILES 31          // ceil(1936/64)
#define ALPHA_C 1500.0f
#define EPS_C   1e-12f

// ---- device scratch (static: no allocations allowed) ----
// g_w layout: [s][k32][c][2]  where pair rows are (k, k+32):
//   g_w[((s*32 + k)*128 + c)*2 + 0] = 2a*cent[k*5+s][c]
//   g_w[((s*32 + k)*128 + c)*2 + 1] = 2a*cent[(k+32)*5+s][c]
__device__ float g_w[5 * 32 * 128 * 2];
__device__ float g_b[MM];                       // [(s*32+k)*2 + j]
__device__ float g_part[NN * TILES * KK * CC];  // per-tile partial accumulators (~8.1 MB)
__device__ float g_sumw[NN * TILES * KK];
__device__ float g_outn[NN * KK * CC];
__device__ float g_rowss[NN * KK];

// ---- f32x2 helpers (ptxas never auto-emits FFMA2; B300 fma pipe is 2x wider via f32x2) ----
__device__ __forceinline__ unsigned long long dup2(float v) {
    unsigned long long r;
    asm("mov.b64 %0, {%1, %1};" : "=l"(r) : "f"(v));
    return r;
}
__device__ __forceinline__ void fma2(unsigned long long& d, unsigned long long a, unsigned long long b) {
    asm("fma.rn.f32x2 %0, %1, %2, %0;" : "+l"(d) : "l"(a), "l"(b));
}
__device__ __forceinline__ float2 unpack2(unsigned long long v) {
    float2 r;
    asm("mov.b64 {%0, %1}, %2;" : "=f"(r.x), "=f"(r.y) : "l"(v));
    return r;
}

// ======================= prep: build interleaved w and b =======================
__global__ void prep_kernel(const float* __restrict__ cent) {
    int m = blockIdx.x * 8 + (threadIdx.x >> 5);
    int lane = threadIdx.x & 31;
    if (m >= MM) return;
    float4 v = *(const float4*)(cent + m * CC + lane * 4);
    float ss = v.x * v.x + v.y * v.y + v.z * v.z + v.w * v.w;
    #pragma unroll
    for (int o = 16; o; o >>= 1) ss += __shfl_xor_sync(0xffffffffu, ss, o);
    int k = m / S1C, s = m % S1C;
    int j = k >> 5, kk = k & 31;
    int pair = s * 32 + kk;
    if (lane == 0) g_b[pair * 2 + j] = -ALPHA_C * sqrtf(ss);
    float* wr = g_w + (pair * 128 + lane * 4) * 2 + j;
    wr[0] = 2.0f * ALPHA_C * v.x;
    wr[2] = 2.0f * ALPHA_C * v.y;
    wr[4] = 2.0f * ALPHA_C * v.z;
    wr[6] = 2.0f * ALPHA_C * v.w;
}

// ======================= fused main kernel =======================
// block = (n, pixel-tile of 64). smem (103680 B) -> 2 CTAs/SM:
//   xs : float2[64 c2][66 p]   pairs {x[2c2][p], x[2c2+1][p]}   (33792 B)
//   wsB: one 32 KB w chunk (s-slice) / later w_assign alias      (33792 B)
//   l0s: float[64 p][68]  s=0 logits                             (17408 B)
//   bts: float[64 p][68]  beta = softmax_s at s=0                (17408 B)
//   bs : float[320]       biases                                 (1280 B)
__global__ __launch_bounds__(512, 2)
void main_kernel(const float* __restrict__ x, float* __restrict__ sa_out) {
    extern __shared__ float smem[];
    float* xs  = smem;             // 8448 floats
    float* wsB = smem + 8448;      // 8448 floats
    float* l0s = smem + 16896;     // 4352 floats
    float* bts = smem + 21248;     // 4352 floats
    float* bs  = smem + 25600;     // 320 floats

    int tid = threadIdx.x;
    int bx = blockIdx.x;
    int n = bx / TILES, tile = bx % TILES;
    int p0 = tile * PT;
    int pvalid = min(PT, PP - p0);

    if (tid < 320) bs[tid] = g_b[tid];

    // ---- load x tile ----
    {
        int c = tid >> 2, lane4 = tid & 3;
        const float* src = x + (n * CC + c) * PP + p0;
        int half = c & 1, c2 = c >> 1;
        #pragma unroll
        for (int u = 0; u < 16; u++) {
            int p = u * 4 + lane4;
            float v = (p0 + p < PP) ? src[p] : 0.0f;
            xs[(c2 * 66 + p) * 2 + half] = v;
        }
    }

    // ---- phase 1: logits GEMM, 5 chunks (one s each), online softmax over s ----
    int pg = tid & 31;   // pixel pair: p = 2*pg + px
    int mg = tid >> 5;   // k-bases: mg and mg+16 (each paired with +32)
    float m8[8], s8[8];  // stream = ki*4 + part*2 + px

    for (int s = 0; s < 5; s++) {
        __syncthreads();
        {   // stream w chunk (32 KB)
            const float4* wsrc = (const float4*)(g_w + s * 8192);
            float4* wdst = (float4*)wsB;
            #pragma unroll
            for (int i = 0; i < 4; i++) wdst[tid + i * 512] = wsrc[tid + i * 512];
        }
        __syncthreads();

        unsigned long long acc[2][2];
        acc[0][0] = 0ull; acc[0][1] = 0ull; acc[1][0] = 0ull; acc[1][1] = 0ull;

        #pragma unroll 4
        for (int c2 = 0; c2 < 64; c2++) {
            float4 xq = *(const float4*)(xs + c2 * 132 + pg * 4);
            unsigned long long xa0 = dup2(xq.x), xb0 = dup2(xq.y);
            unsigned long long xa1 = dup2(xq.z), xb1 = dup2(xq.w);
            #pragma unroll
            for (int ki = 0; ki < 2; ki++) {
                ulonglong2 wv = *(const ulonglong2*)(wsB + (mg + ki * 16) * 256 + c2 * 4);
                fma2(acc[ki][0], wv.x, xa0);
                fma2(acc[ki][0], wv.y, xb0);
                fma2(acc[ki][1], wv.x, xa1);
                fma2(acc[ki][1], wv.y, xb1);
            }
        }

        #pragma unroll
        for (int ki = 0; ki < 2; ki++) {
            int kb = mg + ki * 16;
            float b0 = bs[(s * 32 + kb) * 2 + 0];
            float b1 = bs[(s * 32 + kb) * 2 + 1];
            #pragma unroll
            for (int px = 0; px < 2; px++) {
                float2 l = unpack2(acc[ki][px]);
                float lx = l.x + b0, ly = l.y + b1;
                int p = pg * 2 + px;
                int st0 = ki * 4 + px;        // k = kb
                int st1 = ki * 4 + 2 + px;    // k = kb + 32
                if (s == 0) {
                    l0s[p * 68 + kb]      = lx;
                    l0s[p * 68 + kb + 32] = ly;
                    m8[st0] = lx; s8[st0] = 1.0f;
                    m8[st1] = ly; s8[st1] = 1.0f;
                } else {
                    float nm0 = fmaxf(m8[st0], lx);
                    s8[st0] = s8[st0] * __expf(m8[st0] - nm0) + __expf(lx - nm0);
                    m8[st0] = nm0;
                    float nm1 = fmaxf(m8[st1], ly);
                    s8[st1] = s8[st1] * __expf(m8[st1] - nm1) + __expf(ly - nm1);
                    m8[st1] = nm1;
                }
            }
        }
    }

    // beta = exp(l0 - m)/sum
    #pragma unroll
    for (int ki = 0; ki < 2; ki++) {
        int kb = mg + ki * 16;
        #pragma unroll
        for (int px = 0; px < 2; px++) {
            int p = pg * 2 + px;
            int st0 = ki * 4 + px, st1 = ki * 4 + 2 + px;
            bts[p * 68 + kb]      = __expf(l0s[p * 68 + kb] - m8[st0]) / s8[st0];
            bts[p * 68 + kb + 32] = __expf(l0s[p * 68 + kb + 32] - m8[st1]) / s8[st1];
        }
    }
    __syncthreads();

    // ---- alpha softmax over k (warp per 4 pixels), write w_assign into wsB (alias) ----
    {
        int wid = tid >> 5, lane = tid & 31;
        #pragma unroll
        for (int pi = 0; pi < 4; pi++) {
            int p = wid * 4 + pi;
            float l0a = l0s[p * 68 + lane];
            float l0b = l0s[p * 68 + lane + 32];
            float am = fmaxf(l0a, l0b);
            #pragma unroll
            for (int o = 16; o; o >>= 1) am = fmaxf(am, __shfl_xor_sync(0xffffffffu, am, o));
            float ea = __expf(l0a - am), eb = __expf(l0b - am);
            float es = ea + eb;
            #pragma unroll
            for (int o = 16; o; o >>= 1) es += __shfl_xor_sync(0xffffffffu, es, o);
            float inv = 1.0f / es;
            float sa0 = ea * inv * bts[p * 68 + lane];
            float sa1 = eb * inv * bts[p * 68 + lane + 32];
            float w0 = (p < pvalid) ? (1.0f + sa0) : 0.0f;
            float w1 = (p < pvalid) ? (1.0f + sa1) : 0.0f;
            *(float2*)(wsB + (lane * 66 + p) * 2)        = make_float2(w0, w0);
            *(float2*)(wsB + ((lane + 32) * 66 + p) * 2) = make_float2(w1, w1);
        }
    }
    __syncthreads();

    // ---- write soft_assign (coalesced) ----
    {
        int k = tid >> 3, seg = tid & 7;
        float* dst = sa_out + (n * KK + k) * PP + p0;
        #pragma unroll
        for (int u = 0; u < 8; u++) {
            int p = seg * 8 + u;
            if (p < pvalid) dst[p] = wsB[(k * 66 + p) * 2] - 1.0f;
        }
    }

    // ---- phase 2: out_part[k][c] = sum_p wa[k][p] * x[c][p] ----
    {
        int cg = tid & 31, kg = tid >> 5;
        unsigned long long a2[4][2];
        #pragma unroll
        for (int i = 0; i < 4; i++) { a2[i][0] = 0ull; a2[i][1] = 0ull; }
        #pragma unroll 2
        for (int p = 0; p < 64; p += 2) {
            ulonglong2 xv0 = *(const ulonglong2*)(xs + (cg * 66 + p) * 2);
            ulonglong2 xv1 = *(const ulonglong2*)(xs + ((cg + 32) * 66 + p) * 2);
            #pragma unroll
            for (int q = 0; q < 4; q++) {
                ulonglong2 wv = *(const ulonglong2*)(wsB + ((kg * 4 + q) * 66 + p) * 2);
                fma2(a2[q][0], wv.x, xv0.x);
                fma2(a2[q][0], wv.y, xv0.y);
                fma2(a2[q][1], wv.x, xv1.x);
                fma2(a2[q][1], wv.y, xv1.y);
            }
        }
        float* pb = g_part + bx * 8192;
        #pragma unroll
        for (int q = 0; q < 4; q++) {
            int k = kg * 4 + q;
            #pragma unroll
            for (int j = 0; j < 2; j++) {
                int c2 = cg + 32 * j;
                float2 r = unpack2(a2[q][j]);
                *(float2*)(pb + k * 128 + c2 * 2) = r;
            }
        }
    }

    // ---- sumw partials ----
    if (tid < 64) {
        float s = 0.0f;
        #pragma unroll 8
        for (int p = 0; p < 64; p++) s += wsB[(tid * 66 + p) * 2];
        g_sumw[bx * 64 + tid] = s;
    }
}

// ======================= finalize 1: reduce tiles, subtract rep*sumw, intra-norm =======================
__global__ void finalize1(const float* __restrict__ cent) {
    int n = blockIdx.x >> 6, k = blockIdx.x & 63;
    int c = threadIdx.x;  // 128 threads
    float acc = 0.0f;
    const float* pb = g_part + (n * TILES) * 8192 + k * 128 + c;
    #pragma unroll
    for (int t = 0; t < TILES; t++) acc += pb[t * 8192];
    float sw = 0.0f;
    const float* sb = g_sumw + n * TILES * 64 + k;
    #pragma unroll
    for (int t = 0; t < TILES; t++) sw += sb[t * 64];
    float rep = cent[k * S1C * CC + c];
    float v = acc - rep * sw;
    float ss = v * v;
    #pragma unroll
    for (int o = 16; o; o >>= 1) ss += __shfl_xor_sync(0xffffffffu, ss, o);
    __shared__ float sred[4];
    if ((threadIdx.x & 31) == 0) sred[threadIdx.x >> 5] = ss;
    __syncthreads();
    float tot = sred[0] + sred[1] + sred[2] + sred[3];
    float rn = fmaxf(sqrtf(tot), EPS_C);
    g_outn[(n * 64 + k) * 128 + c] = v / rn;
    if (threadIdx.x == 0) g_rowss[n * 64 + k] = tot / (rn * rn);
}

// ======================= finalize 2: global L2 norm per n (wide grid, redundant sums) =======================
__global__ void finalize2(float* __restrict__ out) {
    int n = blockIdx.x >> 4, seg = blockIdx.x & 15;
    int tid = threadIdx.x;  // 128
    __shared__ float part[4];
    float v = (tid < 64) ? g_rowss[n * 64 + tid] : 0.0f;
    #pragma unroll
    for (int o = 16; o; o >>= 1) v += __shfl_xor_sync(0xffffffffu, v, o);
    if ((tid & 31) == 0) part[tid >> 5] = v;
    __syncthreads();
    float sc = 1.0f / fmaxf(sqrtf(part[0] + part[1] + part[2] + part[3]), EPS_C);
    int base = n * 8192 + seg * 512;
    float4 t = ((const float4*)(g_outn + base))[tid];
    ((float4*)(out + base))[tid] = make_float4(t.x * sc, t.y * sc, t.z * sc, t.w * sc);
}

extern "C" void kernel_launch(void* const* d_in, const int* in_sizes, int n_in,
                              void* d_out, int out_size) {
    const float* x    = (const float*)d_in[0];   // (8,128,44,44)
    const float* cent = (const float*)d_in[1];   // (64,5,128)
    float* out = (float*)d_out;                  // [flat (8,8192) | soft_assign (8,64,1,1936)]
    float* sa = out + NN * KK * CC;

    cudaFuncSetAttribute(main_kernel, cudaFuncAttributeMaxDynamicSharedMemorySize, 103680);

    prep_kernel<<<40, 256>>>(cent);
    main_kernel<<<NN * TILES, 512, 103680>>>(x, sa);
    finalize1<<<NN * KK, 128>>>(cent);
    finalize2<<<NN * 16, 128>>>(out);
}

// round 7
// speedup vs baseline: 1.4934x; 1.4934x over previous
#include <cuda_runtime.h>

#define KK    64
#define S1C   5
#define CC    128
#define MM    320         // KK*S1C
#define PP    1936        // 44*44
#define NN    8
#define PT    128         // pixels per tile
#define TILES 16          // ceil(1936/128)
#define ALPHA_C 1500.0f
#define EPS_C   1e-12f

// ---- device scratch (static: no allocations allowed) ----
// g_w layout: pair P = chunk*80 + s*16 + mg packs rows (k, k+16), k = chunk*32 + mg:
//   g_w[P*256 + c*2 + 0] = 2a*cent[(chunk*32+mg)*5 + s][c]
//   g_w[P*256 + c*2 + 1] = 2a*cent[(chunk*32+mg+16)*5 + s][c]
__device__ float g_w[160 * 256];
__device__ float g_b[MM];                       // [P*2 + j]
__device__ float g_part[NN * TILES * KK * CC];  // per-tile partial accumulators (4.2 MB)
__device__ float g_sumw[NN * TILES * KK];
__device__ float g_outn[NN * KK * CC];
__device__ float g_rowss[NN * KK];

// ---- f32x2 helpers (ptxas never auto-emits FFMA2; B300 fma pipe is 2x wider via f32x2) ----
__device__ __forceinline__ unsigned long long dup2(float v) {
    unsigned long long r;
    asm("mov.b64 %0, {%1, %1};" : "=l"(r) : "f"(v));
    return r;
}
__device__ __forceinline__ void fma2(unsigned long long& d, unsigned long long a, unsigned long long b) {
    asm("fma.rn.f32x2 %0, %1, %2, %0;" : "+l"(d) : "l"(a), "l"(b));
}
__device__ __forceinline__ float2 unpack2(unsigned long long v) {
    float2 r;
    asm("mov.b64 {%0, %1}, %2;" : "=f"(r.x), "=f"(r.y) : "l"(v));
    return r;
}

// ======================= prep: build interleaved w and b =======================
__global__ void prep_kernel(const float* __restrict__ cent) {
    int m = blockIdx.x * 8 + (threadIdx.x >> 5);
    int lane = threadIdx.x & 31;
    if (m >= MM) return;
    float4 v = *(const float4*)(cent + m * CC + lane * 4);
    float ss = v.x * v.x + v.y * v.y + v.z * v.z + v.w * v.w;
    #pragma unroll
    for (int o = 16; o; o >>= 1) ss += __shfl_xor_sync(0xffffffffu, ss, o);
    int k = m / S1C, s = m % S1C;
    int chunk = k >> 5, kk = k & 31;
    int mg = kk & 15, j = kk >> 4;
    int P = chunk * 80 + s * 16 + mg;
    if (lane == 0) g_b[P * 2 + j] = -ALPHA_C * sqrtf(ss);
    float* wr = g_w + (P * 128 + lane * 4) * 2 + j;
    wr[0] = 2.0f * ALPHA_C * v.x;
    wr[2] = 2.0f * ALPHA_C * v.y;
    wr[4] = 2.0f * ALPHA_C * v.z;
    wr[6] = 2.0f * ALPHA_C * v.w;
}

// ======================= fused main kernel =======================
// block = (n, pixel-tile of 128), 128 blocks = 1 wave. smem 158464 B:
//   xs : [64 c2][130 p][2]  pairs {x[2c2][p], x[2c2+1][p]}    66560 B
//   ws : 80 pairs x 256     one 80 KB w chunk / was alias     81920 B
//   red: [128 p][17]        cross-warp alpha reduction         8704 B
//   bs : float[320]         biases                             1280 B
__global__ __launch_bounds__(512, 1)
void main_kernel(const float* __restrict__ x, float* __restrict__ sa_out) {
    extern __shared__ float smem[];
    float* xs  = smem;                    // 16640 floats
    float* ws  = smem + 16640;            // 20480 floats (alias: was 64x130x2 = 16640)
    float* red = smem + 16640 + 20480;    // 2176 floats
    float* bs  = red + 2176;              // 320 floats
    float* was = ws;

    int tid = threadIdx.x;
    int lane = tid & 31;    // pixel quad base p = 4*lane
    int mg = tid >> 5;      // warp id = k-pair base within chunk
    int bx = blockIdx.x;
    int n = bx >> 4, tile = bx & 15;
    int p0 = tile * PT;
    int pvalid = min(PT, PP - p0);   // 128, or 16 on tile 15 (multiple of 4)

    if (tid < 320) bs[tid] = g_b[tid];

    // ---- load x tile: 8 float4 per thread ----
    {
        int c = tid >> 2, t4 = tid & 3;
        int c2 = c >> 1, half = c & 1;
        const float* src = x + (n * CC + c) * PP + p0;
        #pragma unroll
        for (int i = 0; i < 8; i++) {
            int p = t4 * 32 + i * 4;
            float4 v = (p < pvalid) ? *(const float4*)(src + p)
                                    : make_float4(0.f, 0.f, 0.f, 0.f);
            float* d = xs + (c2 * 130 + p) * 2 + half;
            d[0] = v.x; d[2] = v.y; d[4] = v.z; d[6] = v.w;
        }
    }

    // ---- phase 1: logits GEMM (2 chunks of 32 k x 5 s) + register softmax over s ----
    float l0r[16], btr[16];   // idx = ch*8 + k2*4 + px ; k = ch*32 + mg + k2*16
    for (int ch = 0; ch < 2; ch++) {
        __syncthreads();
        {   // stream w chunk (80 KB)
            const float4* wsrc = (const float4*)(g_w + ch * 20480);
            float4* wdst = (float4*)ws;
            #pragma unroll
            for (int i = 0; i < 10; i++) wdst[tid + i * 512] = wsrc[tid + i * 512];
        }
        __syncthreads();

        unsigned long long acc[5][4];
        #pragma unroll
        for (int s = 0; s < 5; s++)
            #pragma unroll
            for (int q = 0; q < 4; q++) acc[s][q] = 0ull;

        #pragma unroll 4
        for (int c2 = 0; c2 < 64; c2++) {
            const float* xr = xs + (c2 * 130 + 4 * lane) * 2;
            float4 xa = *(const float4*)xr;
            float4 xb = *(const float4*)(xr + 4);
            unsigned long long xd0 = dup2(xa.x), xd1 = dup2(xa.y);
            unsigned long long xd2 = dup2(xa.z), xd3 = dup2(xa.w);
            unsigned long long xd4 = dup2(xb.x), xd5 = dup2(xb.y);
            unsigned long long xd6 = dup2(xb.z), xd7 = dup2(xb.w);
            #pragma unroll
            for (int s = 0; s < 5; s++) {
                ulonglong2 wv = *(const ulonglong2*)(ws + (s * 16 + mg) * 256 + c2 * 4);
                fma2(acc[s][0], wv.x, xd0); fma2(acc[s][0], wv.y, xd1);
                fma2(acc[s][1], wv.x, xd2); fma2(acc[s][1], wv.y, xd3);
                fma2(acc[s][2], wv.x, xd4); fma2(acc[s][2], wv.y, xd5);
                fma2(acc[s][3], wv.x, xd6); fma2(acc[s][3], wv.y, xd7);
            }
        }

        float b0[5], b1[5];
        #pragma unroll
        for (int s = 0; s < 5; s++) {
            b0[s] = bs[(ch * 80 + s * 16 + mg) * 2 + 0];
            b1[s] = bs[(ch * 80 + s * 16 + mg) * 2 + 1];
        }
        #pragma unroll
        for (int px = 0; px < 4; px++) {
            float lx[5], ly[5];
            #pragma unroll
            for (int s = 0; s < 5; s++) {
                float2 a = unpack2(acc[s][px]);
                lx[s] = a.x + b0[s];
                ly[s] = a.y + b1[s];
            }
            float m0 = fmaxf(fmaxf(fmaxf(lx[0], lx[1]), fmaxf(lx[2], lx[3])), lx[4]);
            float e0 = __expf(lx[0] - m0);
            float s0 = e0 + __expf(lx[1] - m0) + __expf(lx[2] - m0)
                          + __expf(lx[3] - m0) + __expf(lx[4] - m0);
            l0r[ch * 8 + px] = lx[0];
            btr[ch * 8 + px] = e0 * __frcp_rn(s0);
            float m1 = fmaxf(fmaxf(fmaxf(ly[0], ly[1]), fmaxf(ly[2], ly[3])), ly[4]);
            float e1 = __expf(ly[0] - m1);
            float s1 = e1 + __expf(ly[1] - m1) + __expf(ly[2] - m1)
                          + __expf(ly[3] - m1) + __expf(ly[4] - m1);
            l0r[ch * 8 + 4 + px] = ly[0];
            btr[ch * 8 + 4 + px] = e1 * __frcp_rn(s1);
        }
    }

    // ---- alpha softmax over k: cross-warp reduction via red[p][17] ----
    #pragma unroll
    for (int px = 0; px < 4; px++) {
        float mx = fmaxf(fmaxf(l0r[px], l0r[4 + px]), fmaxf(l0r[8 + px], l0r[12 + px]));
        red[(4 * lane + px) * 17 + mg] = mx;
    }
    __syncthreads();
    float amax[4];
    #pragma unroll
    for (int px = 0; px < 4; px++) {
        float m = -1e30f;
        #pragma unroll
        for (int i = 0; i < 16; i++) m = fmaxf(m, red[(4 * lane + px) * 17 + i]);
        amax[px] = m;
    }
    __syncthreads();
    #pragma unroll
    for (int px = 0; px < 4; px++) {
        float s = __expf(l0r[px] - amax[px]) + __expf(l0r[4 + px] - amax[px])
                + __expf(l0r[8 + px] - amax[px]) + __expf(l0r[12 + px] - amax[px]);
        red[(4 * lane + px) * 17 + mg] = s;
    }
    __syncthreads();
    float ainv[4];
    #pragma unroll
    for (int px = 0; px < 4; px++) {
        float s = 0.f;
        #pragma unroll
        for (int i = 0; i < 16; i++) s += red[(4 * lane + px) * 17 + i];
        ainv[px] = __frcp_rn(s);
    }

    // ---- w_assign to smem (alias over ws), soft_assign to gmem, sumw ----
    #pragma unroll
    for (int ch = 0; ch < 2; ch++)
        #pragma unroll
        for (int k2 = 0; k2 < 2; k2++) {
            int k = ch * 32 + mg + k2 * 16;
            float sav[4];
            float sw = 0.f;
            #pragma unroll
            for (int px = 0; px < 4; px++) {
                int idx = ch * 8 + k2 * 4 + px;
                float sa = __expf(l0r[idx] - amax[px]) * ainv[px] * btr[idx];
                int p = 4 * lane + px;
                float wa = (p < pvalid) ? (1.0f + sa) : 0.0f;
                sav[px] = sa;
                sw += wa;
                *(float2*)(was + (k * 130 + p) * 2) = make_float2(wa, wa);
            }
            if (4 * lane < pvalid)
                *(float4*)(sa_out + (n * KK + k) * PP + p0 + 4 * lane) =
                    make_float4(sav[0], sav[1], sav[2], sav[3]);
            #pragma unroll
            for (int o = 16; o; o >>= 1) sw += __shfl_xor_sync(0xffffffffu, sw, o);
            if (lane == 0) g_sumw[bx * 64 + k] = sw;
        }
    __syncthreads();

    // ---- phase 2: out_part[k][c] = sum_p wa[k][p] * x[c][p] ----
    {
        int cg = lane, kg = mg;   // k = kg*4+q ; c2 = cg and cg+32
        unsigned long long a2[4][2];
        #pragma unroll
        for (int q = 0; q < 4; q++) { a2[q][0] = 0ull; a2[q][1] = 0ull; }
        #pragma unroll 2
        for (int p = 0; p < PT; p += 2) {
            ulonglong2 xv0 = *(const ulonglong2*)(xs + (cg * 130 + p) * 2);
            ulonglong2 xv1 = *(const ulonglong2*)(xs + ((cg + 32) * 130 + p) * 2);
            #pragma unroll
            for (int q = 0; q < 4; q++) {
                ulonglong2 wv = *(const ulonglong2*)(was + ((kg * 4 + q) * 130 + p) * 2);
                fma2(a2[q][0], wv.x, xv0.x);
                fma2(a2[q][0], wv.y, xv0.y);
                fma2(a2[q][1], wv.x, xv1.x);
                fma2(a2[q][1], wv.y, xv1.y);
            }
        }
        float* pb = g_part + bx * 8192;
        #pragma unroll
        for (int q = 0; q < 4; q++) {
            int k = kg * 4 + q;
            #pragma unroll
            for (int j = 0; j < 2; j++) {
                int c2 = cg + 32 * j;
                float2 r = unpack2(a2[q][j]);
                *(float2*)(pb + k * 128 + c2 * 2) = r;
            }
        }
    }
}

// ======================= finalize 1: reduce tiles, subtract rep*sumw, intra-norm =======================
__global__ void finalize1(const float* __restrict__ cent) {
    int n = blockIdx.x >> 6, k = blockIdx.x & 63;
    int c = threadIdx.x;  // 128 threads
    float acc = 0.0f;
    const float* pb = g_part + (n * TILES) * 8192 + k * 128 + c;
    #pragma unroll
    for (int t = 0; t < TILES; t++) acc += pb[t * 8192];
    float sw = 0.0f;
    const float* sb = g_sumw + n * TILES * 64 + k;
    #pragma unroll
    for (int t = 0; t < TILES; t++) sw += sb[t * 64];
    float rep = cent[k * S1C * CC + c];
    float v = acc - rep * sw;
    float ss = v * v;
    #pragma unroll
    for (int o = 16; o; o >>= 1) ss += __shfl_xor_sync(0xffffffffu, ss, o);
    __shared__ float sred[4];
    if ((threadIdx.x & 31) == 0) sred[threadIdx.x >> 5] = ss;
    __syncthreads();
    float tot = sred[0] + sred[1] + sred[2] + sred[3];
    float rn = fmaxf(sqrtf(tot), EPS_C);
    g_outn[(n * 64 + k) * 128 + c] = v / rn;
    if (threadIdx.x == 0) g_rowss[n * 64 + k] = tot / (rn * rn);
}

// ======================= finalize 2: global L2 norm per n (wide grid, redundant sums) =======================
__global__ void finalize2(float* __restrict__ out) {
    int n = blockIdx.x >> 4, seg = blockIdx.x & 15;
    int tid = threadIdx.x;  // 128
    __shared__ float part[4];
    float v = (tid < 64) ? g_rowss[n * 64 + tid] : 0.0f;
    #pragma unroll
    for (int o = 16; o; o >>= 1) v += __shfl_xor_sync(0xffffffffu, v, o);
    if ((tid & 31) == 0) part[tid >> 5] = v;
    __syncthreads();
    float sc = 1.0f / fmaxf(sqrtf(part[0] + part[1] + part[2] + part[3]), EPS_C);
    int base = n * 8192 + seg * 512;
    float4 t = ((const float4*)(g_outn + base))[tid];
    ((float4*)(out + base))[tid] = make_float4(t.x * sc, t.y * sc, t.z * sc, t.w * sc);
}

extern "C" void kernel_launch(void* const* d_in, const int* in_sizes, int n_in,
                              void* d_out, int out_size) {
    const float* x    = (const float*)d_in[0];   // (8,128,44,44)
    const float* cent = (const float*)d_in[1];   // (64,5,128)
    float* out = (float*)d_out;                  // [flat (8,8192) | soft_assign (8,64,1,1936)]
    float* sa = out + NN * KK * CC;

    cudaFuncSetAttribute(main_kernel, cudaFuncAttributeMaxDynamicSharedMemorySize, 158464);

    prep_kernel<<<40, 256>>>(cent);
    main_kernel<<<NN * TILES, 512, 158464>>>(x, sa);
    finalize1<<<NN * KK, 128>>>(cent);
    finalize2<<<NN * 16, 128>>>(out);
}